// round 4
// baseline (speedup 1.0000x reference)
#include <cuda_runtime.h>
#include <math.h>
#include <float.h>

#define NA 5
#define NC 80
#define MAXT 50
#define HF 38
#define WF 38
#define SPATIAL (HF*WF)            // 1444
#define CELLS_PER_B (NA*SPATIAL)   // 7220
#define BLOCK 256
#define BLOCKS_PER_B ((CELLS_PER_B + BLOCK - 1)/BLOCK)  // 29

__constant__ float c_anch[NA*2] = {
    0.57273f, 0.677385f,
    1.87446f, 2.06253f,
    3.33843f, 5.47434f,
    7.88282f, 3.52778f,
    9.77052f, 9.16828f
};

__device__ double g_sum_main;   // coord loss + conf loss
__device__ double g_sum_ce;     // sum of obj * cross-entropy
__device__ int    g_nobj;       // number of obj cells

__global__ void init_k() {
    g_sum_main = 0.0;
    g_sum_ce   = 0.0;
    g_nobj     = 0;
}

__global__ void __launch_bounds__(BLOCK) main_k(const float* __restrict__ pred,
                                                const float* __restrict__ tgt) {
    // Per-target (GT box) data for this batch, built cooperatively.
    __shared__ float s_x1[MAXT], s_y1[MAXT], s_x2[MAXT], s_y2[MAXT], s_area[MAXT];
    __shared__ float s_tx[MAXT], s_ty[MAXT], s_tw[MAXT], s_th[MAXT];
    __shared__ int   s_key[MAXT], s_cls[MAXT];
    __shared__ unsigned char s_validf[MAXT];
    __shared__ int   s_nvalid;

    const int b   = blockIdx.y;
    const int tid = threadIdx.x;

    if (tid < MAXT) {
        const float* tp = tgt + (size_t)(b*MAXT + tid)*5;
        float cls = tp[0], cx = tp[1], cy = tp[2], wn = tp[3], hn = tp[4];
        s_validf[tid] = (cx != -1.0f);
        float gx = cx * WF, gy = cy * HF, gw = wn * WF, gh = hn * HF;
        float garea = gw * gh;
        // best anchor by co-centered IoU (first max wins, matching argmax)
        int bn = 0; float best = -1.0f;
        #pragma unroll
        for (int n = 0; n < NA; n++) {
            float aw = c_anch[2*n], ah = c_anch[2*n+1];
            float inter = fminf(gw, aw) * fminf(gh, ah);
            float uni   = garea + aw*ah - inter;
            float iou   = (uni > 0.0f) ? inter/uni : 0.0f;
            if (iou > best) { best = iou; bn = n; }
        }
        int gi = min(max((int)gx, 0), WF-1);
        int gj = min(max((int)gy, 0), HF-1);
        s_key[tid] = (bn*HF + gj)*WF + gi;
        s_tx[tid]  = gx - (float)gi;
        s_ty[tid]  = gy - (float)gj;
        float aw = c_anch[2*bn], ah = c_anch[2*bn+1];
        s_tw[tid]  = logf(gw / aw);   // used only when valid
        s_th[tid]  = logf(gh / ah);
        s_cls[tid] = min(max((int)cls, 0), NC-1);
        s_x1[tid]  = gx - gw*0.5f;  s_x2[tid] = gx + gw*0.5f;
        s_y1[tid]  = gy - gh*0.5f;  s_y2[tid] = gy + gh*0.5f;
        s_area[tid]= garea;
    }
    __syncthreads();
    if (tid == 0) {
        int n = 0;
        while (n < MAXT && s_validf[n]) n++;   // cumprod semantics: stop at first invalid
        s_nvalid = n;
    }
    __syncthreads();
    const int nv = s_nvalid;

    const int cell = blockIdx.x * BLOCK + tid;
    float contrib = 0.0f;   // coord + conf contribution of this cell
    float ce      = 0.0f;   // cross-entropy contribution (obj cells only)
    int   isobj   = 0;

    if (cell < CELLS_PER_B) {
        const int a   = cell / SPATIAL;
        const int rem = cell - a * SPATIAL;
        const int j   = rem / WF;
        const int i   = rem - j * WF;

        const float* base = pred + ((size_t)b*(NA*(5+NC)) + (size_t)a*(5+NC)) * SPATIAL + rem;
        float x  = base[0];
        float y  = base[SPATIAL];
        float w  = base[2*SPATIAL];
        float h  = base[3*SPATIAL];
        float cf = base[4*SPATIAL];

        float sx = 1.0f / (1.0f + expf(-x));
        float sy = 1.0f / (1.0f + expf(-y));
        float sc = 1.0f / (1.0f + expf(-cf));

        float bx = sx + (float)i;
        float by = sy + (float)j;
        float bw = expf(w) * c_anch[2*a];
        float bh = expf(h) * c_anch[2*a+1];

        float px1 = bx - bw*0.5f, px2 = bx + bw*0.5f;
        float py1 = by - bh*0.5f, py2 = by + bh*0.5f;
        float parea = bw * bh;

        const int mykey = (a*HF + j)*WF + i;

        float maxiou = 0.0f;
        int   owner  = -1;
        float tconf  = 0.0f;
        for (int t = 0; t < nv; t++) {
            float cw  = fminf(px2, s_x2[t]) - fmaxf(px1, s_x1[t]);
            float chh = fminf(py2, s_y2[t]) - fmaxf(py1, s_y1[t]);
            float inter = (cw > 0.0f && chh > 0.0f) ? cw * chh : 0.0f;
            float uni   = parea + s_area[t] - inter;
            float iou   = (uni > 0.0f) ? inter/uni : 0.0f;
            maxiou = fmaxf(maxiou, iou);
            if (s_key[t] == mykey) { owner = t; tconf = iou; }  // last valid target wins
        }

        if (owner >= 0) {
            float dx = sx - s_tx[owner];
            float dy = sy - s_ty[owner];
            float dw = w  - s_tw[owner];
            float dh = h  - s_th[owner];
            contrib = dx*dx + dy*dy + dw*dw + dh*dh;        // COORD_SCALE = 1
            float dc = sc - tconf;
            contrib += 5.0f * dc * dc;                       // OBJ_SCALE = 5
            // cross-entropy over 80 classes (online logsumexp, single strided pass)
            const float* lg = base + 5*SPATIAL;
            const int tc = s_cls[owner];
            float m = -FLT_MAX, ssum = 0.0f, tlogit = 0.0f;
            for (int c = 0; c < NC; c++) {
                float v = lg[(size_t)c * SPATIAL];
                if (c == tc) tlogit = v;
                if (v > m) { ssum = ssum * expf(m - v) + 1.0f; m = v; }
                else       { ssum += expf(v - m); }
            }
            ce = (m + logf(ssum)) - tlogit;
            isobj = 1;
        } else {
            if (maxiou <= 0.6f) contrib = sc * sc;           // NOOBJ_SCALE = 1, tconf = 0
        }
    }

    // block reduction: warp shuffle then smem across warps
    float v0 = contrib, v1 = ce; int v2 = isobj;
    #pragma unroll
    for (int o = 16; o > 0; o >>= 1) {
        v0 += __shfl_down_sync(0xFFFFFFFFu, v0, o);
        v1 += __shfl_down_sync(0xFFFFFFFFu, v1, o);
        v2 += __shfl_down_sync(0xFFFFFFFFu, v2, o);
    }
    __shared__ float r0[BLOCK/32], r1[BLOCK/32];
    __shared__ int   r2[BLOCK/32];
    const int wid = tid >> 5, lane = tid & 31;
    if (lane == 0) { r0[wid] = v0; r1[wid] = v1; r2[wid] = v2; }
    __syncthreads();
    if (tid == 0) {
        float a0 = 0.0f, a1 = 0.0f; int a2 = 0;
        #pragma unroll
        for (int k = 0; k < BLOCK/32; k++) { a0 += r0[k]; a1 += r1[k]; a2 += r2[k]; }
        atomicAdd(&g_sum_main, (double)a0);
        if (a1 != 0.0f) atomicAdd(&g_sum_ce, (double)a1);
        if (a2)         atomicAdd(&g_nobj, a2);
    }
}

__global__ void fin_k(float* __restrict__ out) {
    double n = (double)g_nobj;
    if (n < 1.0) n = 1.0;
    out[0] = (float)(g_sum_main + g_sum_ce / n);
}

extern "C" void kernel_launch(void* const* d_in, const int* in_sizes, int n_in,
                              void* d_out, int out_size) {
    const float* pred = (const float*)d_in[0];
    const float* tgt  = (const float*)d_in[1];
    int B = in_sizes[0] / (NA * (5 + NC) * SPATIAL);   // 64 for this problem

    init_k<<<1, 1>>>();
    dim3 grid(BLOCKS_PER_B, B);
    main_k<<<grid, BLOCK>>>(pred, tgt);
    fin_k<<<1, 1>>>((float*)d_out);
}

// round 5
// speedup vs baseline: 1.1203x; 1.1203x over previous
#include <cuda_runtime.h>
#include <math.h>
#include <float.h>

#define NA 5
#define NC 80
#define MAXT 50
#define HF 38
#define WF 38
#define SPATIAL (HF*WF)            // 1444
#define CELLS_PER_B (NA*SPATIAL)   // 7220
#define BLOCK 256
#define BLOCKS_PER_B ((CELLS_PER_B + BLOCK - 1)/BLOCK)  // 29
#define BATCH 64
#define NBLK (BLOCKS_PER_B*BATCH)  // 1856
#define FULLMASK 0xFFFFFFFFu

__constant__ float c_anch[NA*2] = {
    0.57273f, 0.677385f,
    1.87446f, 2.06253f,
    3.33843f, 5.47434f,
    7.88282f, 3.52778f,
    9.77052f, 9.16828f
};

// Per-block partials (fully overwritten each run -> no init kernel needed)
__device__ float        g_part_main[NBLK];
__device__ float        g_part_ce[NBLK];
__device__ int          g_part_nobj[NBLK];
__device__ unsigned int g_ticket;          // zero-initialized; last block resets it

__global__ void __launch_bounds__(BLOCK) yolo_k(const float* __restrict__ pred,
                                                const float* __restrict__ tgt,
                                                float* __restrict__ out) {
    __shared__ float s_x1[MAXT], s_y1[MAXT], s_x2[MAXT], s_y2[MAXT], s_area[MAXT];
    __shared__ float s_tx[MAXT], s_ty[MAXT], s_tw[MAXT], s_th[MAXT];
    __shared__ int   s_key[MAXT], s_cls[MAXT];
    __shared__ unsigned char s_validf[MAXT];
    __shared__ int   s_nvalid;
    __shared__ bool  s_last;

    const int b   = blockIdx.y;
    const int tid = threadIdx.x;
    const int bid = blockIdx.y * BLOCKS_PER_B + blockIdx.x;

    if (tid < MAXT) {
        const float* tp = tgt + (size_t)(b*MAXT + tid)*5;
        float cls = tp[0], cx = tp[1], cy = tp[2], wn = tp[3], hn = tp[4];
        s_validf[tid] = (cx != -1.0f);
        float gx = cx * WF, gy = cy * HF, gw = wn * WF, gh = hn * HF;
        float garea = gw * gh;
        int bn = 0; float best = -1.0f;
        #pragma unroll
        for (int n = 0; n < NA; n++) {
            float aw = c_anch[2*n], ah = c_anch[2*n+1];
            float inter = fminf(gw, aw) * fminf(gh, ah);
            float uni   = garea + aw*ah - inter;
            float iou   = (uni > 0.0f) ? inter/uni : 0.0f;
            if (iou > best) { best = iou; bn = n; }
        }
        int gi = min(max((int)gx, 0), WF-1);
        int gj = min(max((int)gy, 0), HF-1);
        s_key[tid] = (bn*HF + gj)*WF + gi;
        s_tx[tid]  = gx - (float)gi;
        s_ty[tid]  = gy - (float)gj;
        float aw = c_anch[2*bn], ah = c_anch[2*bn+1];
        s_tw[tid]  = logf(gw / aw);
        s_th[tid]  = logf(gh / ah);
        s_cls[tid] = min(max((int)cls, 0), NC-1);
        s_x1[tid]  = gx - gw*0.5f;  s_x2[tid] = gx + gw*0.5f;
        s_y1[tid]  = gy - gh*0.5f;  s_y2[tid] = gy + gh*0.5f;
        s_area[tid]= garea;
    }
    __syncthreads();
    if (tid == 0) {
        int n = 0;
        while (n < MAXT && s_validf[n]) n++;   // cumprod semantics
        s_nvalid = n;
    }
    __syncthreads();
    const int nv = s_nvalid;

    const int cell = blockIdx.x * BLOCK + tid;
    float contrib = 0.0f;
    float ce      = 0.0f;
    int   isobj   = 0;
    int   owner   = -1;
    int   tc      = 0;
    const float* base = pred;   // safe default for inactive lanes
    float sx = 0.f, sy = 0.f, sc = 0.f, w = 0.f, h = 0.f, tconf = 0.f;

    if (cell < CELLS_PER_B) {
        const int a   = cell / SPATIAL;
        const int rem = cell - a * SPATIAL;
        const int j   = rem / WF;
        const int i   = rem - j * WF;

        base = pred + ((size_t)b*(NA*(5+NC)) + (size_t)a*(5+NC)) * SPATIAL + rem;
        float x  = base[0];
        float yv = base[SPATIAL];
        w        = base[2*SPATIAL];
        h        = base[3*SPATIAL];
        float cf = base[4*SPATIAL];

        sx = 1.0f / (1.0f + expf(-x));
        sy = 1.0f / (1.0f + expf(-yv));
        sc = 1.0f / (1.0f + expf(-cf));

        float bx = sx + (float)i;
        float by = sy + (float)j;
        float bw = expf(w) * c_anch[2*a];
        float bh = expf(h) * c_anch[2*a+1];

        float px1 = bx - bw*0.5f, px2 = bx + bw*0.5f;
        float py1 = by - bh*0.5f, py2 = by + bh*0.5f;
        float parea = bw * bh;

        const int mykey = (a*HF + j)*WF + i;

        float maxiou = 0.0f;
        for (int t = 0; t < nv; t++) {
            float cw  = fminf(px2, s_x2[t]) - fmaxf(px1, s_x1[t]);
            float chh = fminf(py2, s_y2[t]) - fmaxf(py1, s_y1[t]);
            float inter = (cw > 0.0f && chh > 0.0f) ? cw * chh : 0.0f;
            float uni   = parea + s_area[t] - inter;
            float iou   = (uni > 0.0f) ? inter/uni : 0.0f;
            maxiou = fmaxf(maxiou, iou);
            if (s_key[t] == mykey) { owner = t; tconf = iou; }  // last valid wins
        }

        if (owner >= 0) {
            float dx = sx - s_tx[owner];
            float dy = sy - s_ty[owner];
            float dw = w  - s_tw[owner];
            float dh = h  - s_th[owner];
            contrib = dx*dx + dy*dy + dw*dw + dh*dh;      // COORD_SCALE = 1
            float dc = sc - tconf;
            contrib += 5.0f * dc * dc;                     // OBJ_SCALE = 5
            tc = s_cls[owner];
            isobj = 1;
        } else {
            if (maxiou <= 0.6f) contrib = sc * sc;         // NOOBJ, tconf = 0
        }
    }

    // ---- Warp-cooperative cross-entropy for obj lanes ----
    // Whole warp computes logsumexp over 80 strided class logits of each obj
    // lane's cell: 3 parallel loads/lane (MLP=80/warp) instead of 80 serial.
    const int lane = tid & 31;
    unsigned int omask = __ballot_sync(FULLMASK, isobj);
    while (omask) {
        int src = __ffs(omask) - 1;
        omask &= omask - 1;
        unsigned long long bcast =
            __shfl_sync(FULLMASK, (unsigned long long)(base + 5*SPATIAL), src);
        const float* lg = (const float*)bcast;
        int tcls = __shfl_sync(FULLMASK, tc, src);

        float v0 = lg[(size_t)lane * SPATIAL];
        float v1 = lg[(size_t)(lane + 32) * SPATIAL];
        float v2 = (lane < NC - 64) ? lg[(size_t)(lane + 64) * SPATIAL] : -FLT_MAX;

        float m = fmaxf(fmaxf(v0, v1), v2);
        #pragma unroll
        for (int o = 16; o > 0; o >>= 1)
            m = fmaxf(m, __shfl_xor_sync(FULLMASK, m, o));

        float s = expf(v0 - m) + expf(v1 - m) + ((lane < NC - 64) ? expf(v2 - m) : 0.0f);
        #pragma unroll
        for (int o = 16; o > 0; o >>= 1)
            s += __shfl_xor_sync(FULLMASK, s, o);

        float tl_cand = (tcls < 32) ? v0 : ((tcls < 64) ? v1 : v2);
        float tl = __shfl_sync(FULLMASK, tl_cand, tcls & 31);

        float ce_val = (m + logf(s)) - tl;
        if (lane == src) ce = ce_val;
    }

    // ---- Block reduction ----
    float r_main = contrib, r_ce = ce; int r_no = isobj;
    #pragma unroll
    for (int o = 16; o > 0; o >>= 1) {
        r_main += __shfl_down_sync(FULLMASK, r_main, o);
        r_ce   += __shfl_down_sync(FULLMASK, r_ce, o);
        r_no   += __shfl_down_sync(FULLMASK, r_no, o);
    }
    __shared__ float w0[BLOCK/32], w1[BLOCK/32];
    __shared__ int   w2[BLOCK/32];
    const int wid = tid >> 5;
    if (lane == 0) { w0[wid] = r_main; w1[wid] = r_ce; w2[wid] = r_no; }
    __syncthreads();
    if (tid == 0) {
        float a0 = 0.f, a1 = 0.f; int a2 = 0;
        #pragma unroll
        for (int k = 0; k < BLOCK/32; k++) { a0 += w0[k]; a1 += w1[k]; a2 += w2[k]; }
        g_part_main[bid] = a0;
        g_part_ce[bid]   = a1;
        g_part_nobj[bid] = a2;
        __threadfence();
        unsigned int t = atomicAdd(&g_ticket, 1u);
        s_last = (t == NBLK - 1);
    }
    __syncthreads();

    // ---- Last block finishes: reduce partials, write result, reset ticket ----
    if (s_last) {
        __threadfence();
        double dm = 0.0, dc = 0.0; int dn = 0;
        for (int k = tid; k < NBLK; k += BLOCK) {
            dm += (double)g_part_main[k];
            dc += (double)g_part_ce[k];
            dn += g_part_nobj[k];
        }
        #pragma unroll
        for (int o = 16; o > 0; o >>= 1) {
            dm += __shfl_down_sync(FULLMASK, dm, o);
            dc += __shfl_down_sync(FULLMASK, dc, o);
            dn += __shfl_down_sync(FULLMASK, dn, o);
        }
        __shared__ double d0[BLOCK/32], d1[BLOCK/32];
        __shared__ int    d2[BLOCK/32];
        if (lane == 0) { d0[wid] = dm; d1[wid] = dc; d2[wid] = dn; }
        __syncthreads();
        if (tid == 0) {
            double sm = 0.0, scc = 0.0; int sn = 0;
            #pragma unroll
            for (int k = 0; k < BLOCK/32; k++) { sm += d0[k]; scc += d1[k]; sn += d2[k]; }
            double n = (double)sn;
            if (n < 1.0) n = 1.0;
            out[0] = (float)(sm + scc / n);
            g_ticket = 0;   // reset for next graph replay
        }
    }
}

extern "C" void kernel_launch(void* const* d_in, const int* in_sizes, int n_in,
                              void* d_out, int out_size) {
    const float* pred = (const float*)d_in[0];
    const float* tgt  = (const float*)d_in[1];
    dim3 grid(BLOCKS_PER_B, BATCH);
    yolo_k<<<grid, BLOCK>>>(pred, tgt, (float*)d_out);
}

// round 8
// speedup vs baseline: 1.5989x; 1.4272x over previous
#include <cuda_runtime.h>
#include <math.h>
#include <float.h>

#define NA 5
#define NC 80
#define MAXT 50
#define HF 38
#define WF 38
#define SPATIAL (HF*WF)            // 1444
#define CELLS_PER_B (NA*SPATIAL)   // 7220
#define BLOCK 256
#define BLOCKS_PER_B ((CELLS_PER_B + BLOCK - 1)/BLOCK)  // 29
#define BATCH 64
#define NBLK (BLOCKS_PER_B*BATCH)  // 1856
#define FULLMASK 0xFFFFFFFFu

__constant__ float c_anch[NA*2] = {
    0.57273f, 0.677385f,
    1.87446f, 2.06253f,
    3.33843f, 5.47434f,
    7.88282f, 3.52778f,
    9.77052f, 9.16828f
};

// Per-block partials (fully overwritten each run -> no init kernel needed)
__device__ float        g_part_main[NBLK];
__device__ float        g_part_ce[NBLK];
__device__ int          g_part_nobj[NBLK];
__device__ unsigned int g_ticket;          // zero-init; last block resets it

__device__ __forceinline__ float fsigmoid(float v) {
    return __frcp_rn(1.0f + __expf(-v));
}

__global__ void __launch_bounds__(BLOCK) yolo_k(const float* __restrict__ pred,
                                                const float* __restrict__ tgt,
                                                float* __restrict__ out) {
    // Packed per-target data: box corners (x1,y1,x2,y2), and {0.375*area, key}
    __shared__ float4 s_box[MAXT];
    __shared__ float2 s_tk[MAXT];          // .x = 0.375*garea, .y = key bits
    __shared__ float  s_area[MAXT];
    __shared__ float  s_tx[MAXT], s_ty[MAXT], s_tw[MAXT], s_th[MAXT];
    __shared__ int    s_cls[MAXT];
    __shared__ unsigned char s_validf[MAXT];
    __shared__ int    s_nvalid;
    __shared__ bool   s_last;

    const int b   = blockIdx.y;
    const int tid = threadIdx.x;
    const int bid = blockIdx.y * BLOCKS_PER_B + blockIdx.x;

    if (tid < MAXT) {
        const float* tp = tgt + (size_t)(b*MAXT + tid)*5;
        float cls = tp[0], cx = tp[1], cy = tp[2], wn = tp[3], hn = tp[4];
        s_validf[tid] = (cx != -1.0f);
        float gx = cx * WF, gy = cy * HF, gw = wn * WF, gh = hn * HF;
        float garea = gw * gh;
        int bn = 0; float best = -1.0f;
        #pragma unroll
        for (int n = 0; n < NA; n++) {
            float aw = c_anch[2*n], ah = c_anch[2*n+1];
            float inter = fminf(gw, aw) * fminf(gh, ah);
            float uni   = garea + aw*ah - inter;
            float iou   = (uni > 0.0f) ? inter/uni : 0.0f;  // exact: matches argmax ties
            if (iou > best) { best = iou; bn = n; }
        }
        int gi = min(max((int)gx, 0), WF-1);
        int gj = min(max((int)gy, 0), HF-1);
        int key = (bn*HF + gj)*WF + gi;
        s_tk[tid]  = make_float2(0.375f * garea, __int_as_float(key));
        s_tx[tid]  = gx - (float)gi;
        s_ty[tid]  = gy - (float)gj;
        float aw = c_anch[2*bn], ah = c_anch[2*bn+1];
        s_tw[tid]  = __logf(gw / aw);
        s_th[tid]  = __logf(gh / ah);
        s_cls[tid] = min(max((int)cls, 0), NC-1);
        s_box[tid] = make_float4(gx - gw*0.5f, gy - gh*0.5f,
                                 gx + gw*0.5f, gy + gh*0.5f);
        s_area[tid]= garea;
    }
    __syncthreads();
    if (tid == 0) {
        int n = 0;
        while (n < MAXT && s_validf[n]) n++;   // cumprod semantics
        s_nvalid = n;
    }
    __syncthreads();
    const int nv = s_nvalid;

    const int cell = blockIdx.x * BLOCK + tid;
    float contrib = 0.0f;
    float ce      = 0.0f;
    int   isobj   = 0;
    int   owner   = -1;
    int   tc      = 0;
    const float* base = pred;   // safe default for inactive lanes
    float sc = 0.f, parea = 0.f;
    float px1 = 0.f, py1 = 0.f, px2 = 0.f, py2 = 0.f;
    float sx = 0.f, sy = 0.f, w = 0.f, h = 0.f;

    if (cell < CELLS_PER_B) {
        const int a   = cell / SPATIAL;
        const int rem = cell - a * SPATIAL;
        const int j   = rem / WF;
        const int i   = rem - j * WF;

        base = pred + ((size_t)b*(NA*(5+NC)) + (size_t)a*(5+NC)) * SPATIAL + rem;
        float x  = base[0];
        float yv = base[SPATIAL];
        w        = base[2*SPATIAL];
        h        = base[3*SPATIAL];
        float cf = base[4*SPATIAL];

        sx = fsigmoid(x);
        sy = fsigmoid(yv);
        sc = fsigmoid(cf);

        float bx = sx + (float)i;
        float by = sy + (float)j;
        float bw = __expf(w) * c_anch[2*a];
        float bh = __expf(h) * c_anch[2*a+1];

        px1 = bx - bw*0.5f; px2 = bx + bw*0.5f;
        py1 = by - bh*0.5f; py2 = by + bh*0.5f;
        parea = bw * bh;
        const float thr_p = 0.375f * parea;

        const float mykeyf = __int_as_float((a*HF + j)*WF + i);

        bool kill = false;       // some GT has IoU > 0.6 with this pred box
        #pragma unroll 2
        for (int t = 0; t < nv; t++) {
            float4 b4 = s_box[t];
            float2 tk = s_tk[t];
            float cw  = fminf(px2, b4.z) - fmaxf(px1, b4.x);
            float chh = fminf(py2, b4.w) - fmaxf(py1, b4.y);
            float inter = cw * chh;
            // iou > 0.6  <=>  inter > 0.375*(parea+garea), valid only if overlap
            kill = kill | ((fminf(cw, chh) > 0.0f) & (inter > thr_p + tk.x));
            if (__float_as_int(tk.y) == __float_as_int(mykeyf)) owner = t;
        }

        if (owner >= 0) {
            // exact IoU for the (rare) owner cell, one division total
            float4 b4 = s_box[owner];
            float cw  = fminf(px2, b4.z) - fmaxf(px1, b4.x);
            float chh = fminf(py2, b4.w) - fmaxf(py1, b4.y);
            float inter = (cw > 0.0f && chh > 0.0f) ? cw * chh : 0.0f;
            float uni   = parea + s_area[owner] - inter;
            float tconf = (uni > 0.0f) ? __fdividef(inter, uni) : 0.0f;

            float dx = sx - s_tx[owner];
            float dy = sy - s_ty[owner];
            float dw = w  - s_tw[owner];
            float dh = h  - s_th[owner];
            contrib = dx*dx + dy*dy + dw*dw + dh*dh;      // COORD_SCALE = 1
            float dc = sc - tconf;
            contrib += 5.0f * dc * dc;                     // OBJ_SCALE = 5
            tc = s_cls[owner];
            isobj = 1;
        } else if (!kill) {
            contrib = sc * sc;                             // NOOBJ, tconf = 0
        }
    }

    // ---- Warp-cooperative cross-entropy for obj lanes ----
    const int lane = tid & 31;
    unsigned int omask = __ballot_sync(FULLMASK, isobj);
    while (omask) {
        int src = __ffs(omask) - 1;
        omask &= omask - 1;
        unsigned long long bcast =
            __shfl_sync(FULLMASK, (unsigned long long)(base + 5*SPATIAL), src);
        const float* lg = (const float*)bcast;
        int tcls = __shfl_sync(FULLMASK, tc, src);

        float v0 = lg[(size_t)lane * SPATIAL];
        float v1 = lg[(size_t)(lane + 32) * SPATIAL];
        float v2 = (lane < NC - 64) ? lg[(size_t)(lane + 64) * SPATIAL] : -FLT_MAX;

        float m = fmaxf(fmaxf(v0, v1), v2);
        #pragma unroll
        for (int o = 16; o > 0; o >>= 1)
            m = fmaxf(m, __shfl_xor_sync(FULLMASK, m, o));

        float s = __expf(v0 - m) + __expf(v1 - m)
                + ((lane < NC - 64) ? __expf(v2 - m) : 0.0f);
        #pragma unroll
        for (int o = 16; o > 0; o >>= 1)
            s += __shfl_xor_sync(FULLMASK, s, o);

        float tl_cand = (tcls < 32) ? v0 : ((tcls < 64) ? v1 : v2);
        float tl = __shfl_sync(FULLMASK, tl_cand, tcls & 31);

        float ce_val = (m + __logf(s)) - tl;
        if (lane == src) ce = ce_val;
    }

    // ---- Block reduction ----
    float r_main = contrib, r_ce = ce; int r_no = isobj;
    #pragma unroll
    for (int o = 16; o > 0; o >>= 1) {
        r_main += __shfl_down_sync(FULLMASK, r_main, o);
        r_ce   += __shfl_down_sync(FULLMASK, r_ce, o);
        r_no   += __shfl_down_sync(FULLMASK, r_no, o);
    }
    __shared__ float w0[BLOCK/32], w1[BLOCK/32];
    __shared__ int   w2[BLOCK/32];
    const int wid = tid >> 5;
    if (lane == 0) { w0[wid] = r_main; w1[wid] = r_ce; w2[wid] = r_no; }
    __syncthreads();
    if (tid == 0) {
        float a0 = 0.f, a1 = 0.f; int a2 = 0;
        #pragma unroll
        for (int k = 0; k < BLOCK/32; k++) { a0 += w0[k]; a1 += w1[k]; a2 += w2[k]; }
        g_part_main[bid] = a0;
        g_part_ce[bid]   = a1;
        g_part_nobj[bid] = a2;
        __threadfence();
        unsigned int t = atomicAdd(&g_ticket, 1u);
        s_last = (t == NBLK - 1);
    }
    __syncthreads();

    // ---- Last block: reduce partials in double, write result, reset ticket ----
    if (s_last) {
        __threadfence();
        double dm = 0.0, dc = 0.0; int dn = 0;
        for (int k = tid; k < NBLK; k += BLOCK) {
            dm += (double)g_part_main[k];
            dc += (double)g_part_ce[k];
            dn += g_part_nobj[k];
        }
        #pragma unroll
        for (int o = 16; o > 0; o >>= 1) {
            dm += __shfl_down_sync(FULLMASK, dm, o);
            dc += __shfl_down_sync(FULLMASK, dc, o);
            dn += __shfl_down_sync(FULLMASK, dn, o);
        }
        __shared__ double d0[BLOCK/32], d1[BLOCK/32];
        __shared__ int    d2[BLOCK/32];
        if (lane == 0) { d0[wid] = dm; d1[wid] = dc; d2[wid] = dn; }
        __syncthreads();
        if (tid == 0) {
            double sm = 0.0, scc = 0.0; int sn = 0;
            #pragma unroll
            for (int k = 0; k < BLOCK/32; k++) { sm += d0[k]; scc += d1[k]; sn += d2[k]; }
            double n = (double)sn;
            if (n < 1.0) n = 1.0;
            out[0] = (float)(sm + scc / n);
            g_ticket = 0;   // reset for next graph replay
        }
    }
}

extern "C" void kernel_launch(void* const* d_in, const int* in_sizes, int n_in,
                              void* d_out, int out_size) {
    const float* pred = (const float*)d_in[0];
    const float* tgt  = (const float*)d_in[1];
    dim3 grid(BLOCKS_PER_B, BATCH);
    yolo_k<<<grid, BLOCK>>>(pred, tgt, (float*)d_out);
}

// round 9
// speedup vs baseline: 1.7504x; 1.0947x over previous
#include <cuda_runtime.h>
#include <math.h>
#include <float.h>

#define NA 5
#define NC 80
#define MAXT 50
#define HF 38
#define WF 38
#define SPATIAL (HF*WF)            // 1444
#define CELLS_PER_B (NA*SPATIAL)   // 7220
#define BLOCK 256
#define CPT 4                      // cells per thread
#define CELLS_PER_BLK (BLOCK*CPT)  // 1024
#define BLOCKS_PER_B ((CELLS_PER_B + CELLS_PER_BLK - 1)/CELLS_PER_BLK)  // 8
#define BATCH 64
#define NBLK (BLOCKS_PER_B*BATCH)  // 512
#define FULLMASK 0xFFFFFFFFu

__constant__ float c_anch[NA*2] = {
    0.57273f, 0.677385f,
    1.87446f, 2.06253f,
    3.33843f, 5.47434f,
    7.88282f, 3.52778f,
    9.77052f, 9.16828f
};

// Per-block partials (fully overwritten each run -> no init kernel needed)
__device__ float        g_part_main[NBLK];
__device__ float        g_part_ce[NBLK];
__device__ int          g_part_nobj[NBLK];
__device__ unsigned int g_ticket;          // zero-init; last block resets it

__device__ __forceinline__ float fsigmoid(float v) {
    return __fdividef(1.0f, 1.0f + __expf(-v));
}

__global__ void __launch_bounds__(BLOCK) yolo_k(const float* __restrict__ pred,
                                                const float* __restrict__ tgt,
                                                float* __restrict__ out) {
    __shared__ float4 s_box[MAXT];         // x1,y1,x2,y2
    __shared__ float2 s_tk[MAXT];          // .x = 0.375*garea, .y = key bits
    __shared__ float  s_area[MAXT];
    __shared__ float  s_tx[MAXT], s_ty[MAXT], s_tw[MAXT], s_th[MAXT];
    __shared__ int    s_cls[MAXT];
    __shared__ unsigned char s_validf[MAXT];
    __shared__ int    s_nvalid;
    __shared__ bool   s_last;

    const int b   = blockIdx.y;
    const int tid = threadIdx.x;
    const int bid = blockIdx.y * BLOCKS_PER_B + blockIdx.x;

    if (tid < MAXT) {
        const float* tp = tgt + (size_t)(b*MAXT + tid)*5;
        float cls = tp[0], cx = tp[1], cy = tp[2], wn = tp[3], hn = tp[4];
        s_validf[tid] = (cx != -1.0f);
        float gx = cx * WF, gy = cy * HF, gw = wn * WF, gh = hn * HF;
        float garea = gw * gh;
        int bn = 0; float best = -1.0f;
        #pragma unroll
        for (int n = 0; n < NA; n++) {
            float aw = c_anch[2*n], ah = c_anch[2*n+1];
            float inter = fminf(gw, aw) * fminf(gh, ah);
            float uni   = garea + aw*ah - inter;
            float iou   = (uni > 0.0f) ? inter/uni : 0.0f;  // exact: argmax ties
            if (iou > best) { best = iou; bn = n; }
        }
        int gi = min(max((int)gx, 0), WF-1);
        int gj = min(max((int)gy, 0), HF-1);
        int key = (bn*HF + gj)*WF + gi;
        s_tk[tid]  = make_float2(0.375f * garea, __int_as_float(key));
        s_tx[tid]  = gx - (float)gi;
        s_ty[tid]  = gy - (float)gj;
        float aw = c_anch[2*bn], ah = c_anch[2*bn+1];
        s_tw[tid]  = __logf(gw / aw);
        s_th[tid]  = __logf(gh / ah);
        s_cls[tid] = min(max((int)cls, 0), NC-1);
        s_box[tid] = make_float4(gx - gw*0.5f, gy - gh*0.5f,
                                 gx + gw*0.5f, gy + gh*0.5f);
        s_area[tid]= garea;
    }
    __syncthreads();
    if (tid == 0) {
        int n = 0;
        while (n < MAXT && s_validf[n]) n++;   // cumprod semantics
        s_nvalid = n;
    }
    __syncthreads();
    const int nv = s_nvalid;

    // ---- Per-thread state for CPT cells (strided by BLOCK => coalesced) ----
    float px1[CPT], px2[CPT], py1[CPT], py2[CPT], thrp[CPT], scv[CPT];
    int   keyi[CPT], off[CPT], owner[CPT];
    bool  kill[CPT];

    const int cell0 = blockIdx.x * CELLS_PER_BLK + tid;
    const int boff  = b * (NA*(5+NC)) * SPATIAL;

    #pragma unroll
    for (int k = 0; k < CPT; k++) {
        const int cell = cell0 + k * BLOCK;
        owner[k] = -1;
        if (cell < CELLS_PER_B) {
            const int a   = cell / SPATIAL;
            const int rem = cell - a * SPATIAL;
            const int j   = rem / WF;
            const int i   = rem - j * WF;
            off[k] = boff + a*(5+NC)*SPATIAL + rem;
            const float* bp = pred + off[k];
            float x  = bp[0];
            float yv = bp[SPATIAL];
            float w  = bp[2*SPATIAL];
            float h  = bp[3*SPATIAL];
            float cf = bp[4*SPATIAL];
            float sx = fsigmoid(x);
            float sy = fsigmoid(yv);
            scv[k]   = fsigmoid(cf);
            float bx = sx + (float)i;
            float by = sy + (float)j;
            float bw = __expf(w) * c_anch[2*a];
            float bh = __expf(h) * c_anch[2*a+1];
            px1[k] = bx - bw*0.5f; px2[k] = bx + bw*0.5f;
            py1[k] = by - bh*0.5f; py2[k] = by + bh*0.5f;
            thrp[k] = 0.375f * (bw * bh);
            keyi[k] = (a*HF + j)*WF + i;
            kill[k] = false;
        } else {
            off[k] = boff;
            px1[k]=px2[k]=py1[k]=py2[k]=0.f; thrp[k]=0.f; scv[k]=0.f;
            keyi[k] = -1;
            kill[k] = true;     // forces zero contribution
        }
    }

    // ---- Hot loop: 2 LDS serve 4 independent cells (ILP hides latency) ----
    for (int t = 0; t < nv; t++) {
        float4 b4 = s_box[t];
        float2 tk = s_tk[t];
        int    tkey = __float_as_int(tk.y);
        #pragma unroll
        for (int k = 0; k < CPT; k++) {
            float cw  = fminf(px2[k], b4.z) - fmaxf(px1[k], b4.x);
            float chh = fminf(py2[k], b4.w) - fmaxf(py1[k], b4.y);
            float inter = cw * chh;
            kill[k] = kill[k] | ((fminf(cw, chh) > 0.0f) & (inter > thrp[k] + tk.x));
            if (tkey == keyi[k]) owner[k] = t;   // last valid target wins
        }
    }

    // ---- Epilogue per cell ----
    float contrib = 0.0f, ce = 0.0f;
    int   nobj = 0;
    int   tcv[CPT];
    bool  isobj[CPT];

    #pragma unroll
    for (int k = 0; k < CPT; k++) {
        isobj[k] = false; tcv[k] = 0;
        if (owner[k] >= 0) {
            const int o = owner[k];
            // rare path: reload raw preds (L2-hot) and recompute exactly
            const float* bp = pred + off[k];
            float x  = bp[0];
            float yv = bp[SPATIAL];
            float w  = bp[2*SPATIAL];
            float h  = bp[3*SPATIAL];
            float sx = fsigmoid(x);
            float sy = fsigmoid(yv);
            const int a = keyi[k] / SPATIAL;
            float bw = __expf(w) * c_anch[2*a];
            float bh = __expf(h) * c_anch[2*a+1];
            float parea = bw * bh;
            float4 b4 = s_box[o];
            float cw  = fminf(px2[k], b4.z) - fmaxf(px1[k], b4.x);
            float chh = fminf(py2[k], b4.w) - fmaxf(py1[k], b4.y);
            float inter = (cw > 0.0f && chh > 0.0f) ? cw * chh : 0.0f;
            float uni   = parea + s_area[o] - inter;
            float tconf = (uni > 0.0f) ? __fdividef(inter, uni) : 0.0f;
            float dx = sx - s_tx[o];
            float dy = sy - s_ty[o];
            float dw = w  - s_tw[o];
            float dh = h  - s_th[o];
            contrib += dx*dx + dy*dy + dw*dw + dh*dh;     // COORD_SCALE = 1
            float dc = scv[k] - tconf;
            contrib += 5.0f * dc * dc;                     // OBJ_SCALE = 5
            tcv[k] = s_cls[o];
            isobj[k] = true;
            nobj++;
        } else if (!kill[k]) {
            contrib += scv[k] * scv[k];                    // NOOBJ, tconf = 0
        }
    }

    // ---- Warp-cooperative cross-entropy for obj cells (rare) ----
    const int lane = tid & 31;
    #pragma unroll
    for (int k = 0; k < CPT; k++) {
        unsigned int omask = __ballot_sync(FULLMASK, isobj[k]);
        while (omask) {
            int src = __ffs(omask) - 1;
            omask &= omask - 1;
            int offb = __shfl_sync(FULLMASK, off[k], src);
            int tcls = __shfl_sync(FULLMASK, tcv[k], src);
            const float* lg = pred + offb + 5*SPATIAL;

            float v0 = lg[(size_t)lane * SPATIAL];
            float v1 = lg[(size_t)(lane + 32) * SPATIAL];
            float v2 = (lane < NC - 64) ? lg[(size_t)(lane + 64) * SPATIAL] : -FLT_MAX;

            float m = fmaxf(fmaxf(v0, v1), v2);
            #pragma unroll
            for (int o = 16; o > 0; o >>= 1)
                m = fmaxf(m, __shfl_xor_sync(FULLMASK, m, o));

            float s = __expf(v0 - m) + __expf(v1 - m)
                    + ((lane < NC - 64) ? __expf(v2 - m) : 0.0f);
            #pragma unroll
            for (int o = 16; o > 0; o >>= 1)
                s += __shfl_xor_sync(FULLMASK, s, o);

            float tl_cand = (tcls < 32) ? v0 : ((tcls < 64) ? v1 : v2);
            float tl = __shfl_sync(FULLMASK, tl_cand, tcls & 31);

            float ce_val = (m + __logf(s)) - tl;
            if (lane == src) ce += ce_val;
        }
    }

    // ---- Block reduction ----
    float r_main = contrib, r_ce = ce; int r_no = nobj;
    #pragma unroll
    for (int o = 16; o > 0; o >>= 1) {
        r_main += __shfl_down_sync(FULLMASK, r_main, o);
        r_ce   += __shfl_down_sync(FULLMASK, r_ce, o);
        r_no   += __shfl_down_sync(FULLMASK, r_no, o);
    }
    __shared__ float w0[BLOCK/32], w1[BLOCK/32];
    __shared__ int   w2[BLOCK/32];
    const int wid = tid >> 5;
    if (lane == 0) { w0[wid] = r_main; w1[wid] = r_ce; w2[wid] = r_no; }
    __syncthreads();
    if (tid == 0) {
        float a0 = 0.f, a1 = 0.f; int a2 = 0;
        #pragma unroll
        for (int k = 0; k < BLOCK/32; k++) { a0 += w0[k]; a1 += w1[k]; a2 += w2[k]; }
        g_part_main[bid] = a0;
        g_part_ce[bid]   = a1;
        g_part_nobj[bid] = a2;
        __threadfence();
        unsigned int t = atomicAdd(&g_ticket, 1u);
        s_last = (t == NBLK - 1);
    }
    __syncthreads();

    // ---- Last block: reduce partials in double, write result, reset ticket ----
    if (s_last) {
        __threadfence();
        double dm = 0.0, dc = 0.0; int dn = 0;
        for (int k = tid; k < NBLK; k += BLOCK) {
            dm += (double)g_part_main[k];
            dc += (double)g_part_ce[k];
            dn += g_part_nobj[k];
        }
        #pragma unroll
        for (int o = 16; o > 0; o >>= 1) {
            dm += __shfl_down_sync(FULLMASK, dm, o);
            dc += __shfl_down_sync(FULLMASK, dc, o);
            dn += __shfl_down_sync(FULLMASK, dn, o);
        }
        __shared__ double d0[BLOCK/32], d1[BLOCK/32];
        __shared__ int    d2[BLOCK/32];
        if (lane == 0) { d0[wid] = dm; d1[wid] = dc; d2[wid] = dn; }
        __syncthreads();
        if (tid == 0) {
            double sm = 0.0, scc = 0.0; int sn = 0;
            #pragma unroll
            for (int k = 0; k < BLOCK/32; k++) { sm += d0[k]; scc += d1[k]; sn += d2[k]; }
            double n = (double)sn;
            if (n < 1.0) n = 1.0;
            out[0] = (float)(sm + scc / n);
            g_ticket = 0;   // reset for next graph replay
        }
    }
}

extern "C" void kernel_launch(void* const* d_in, const int* in_sizes, int n_in,
                              void* d_out, int out_size) {
    const float* pred = (const float*)d_in[0];
    const float* tgt  = (const float*)d_in[1];
    dim3 grid(BLOCKS_PER_B, BATCH);
    yolo_k<<<grid, BLOCK>>>(pred, tgt, (float*)d_out);
}

// round 10
// speedup vs baseline: 1.7744x; 1.0137x over previous
#include <cuda_runtime.h>
#include <math.h>
#include <float.h>

#define NA 5
#define NC 80
#define MAXT 50
#define HF 38
#define WF 38
#define SPATIAL (HF*WF)            // 1444
#define CELLS_PER_B (NA*SPATIAL)   // 7220
#define BLOCK 128
#define CPT 4                      // cells per thread
#define CELLS_PER_BLK (BLOCK*CPT)  // 512
#define BLOCKS_PER_B ((CELLS_PER_B + CELLS_PER_BLK - 1)/CELLS_PER_BLK)  // 15
#define BATCH 64
#define NBLK (BLOCKS_PER_B*BATCH)  // 960
#define FULLMASK 0xFFFFFFFFu

__constant__ float c_anch[NA*2] = {
    0.57273f, 0.677385f,
    1.87446f, 2.06253f,
    3.33843f, 5.47434f,
    7.88282f, 3.52778f,
    9.77052f, 9.16828f
};

// Per-block partials (fully overwritten each run -> no init kernel needed)
__device__ float        g_part_main[NBLK];
__device__ float        g_part_ce[NBLK];
__device__ int          g_part_nobj[NBLK];
__device__ unsigned int g_ticket;          // zero-init; last block resets it

__device__ __forceinline__ float fsigmoid(float v) {
    return __fdividef(1.0f, 1.0f + __expf(-v));
}

__global__ void __launch_bounds__(BLOCK) yolo_k(const float* __restrict__ pred,
                                                const float* __restrict__ tgt,
                                                float* __restrict__ out) {
    __shared__ float4 s_box[MAXT];         // x1,y1,x2,y2
    __shared__ float2 s_tk[MAXT];          // .x = 0.375*garea, .y = key bits
    __shared__ float  s_area[MAXT];
    __shared__ float  s_tx[MAXT], s_ty[MAXT], s_tw[MAXT], s_th[MAXT];
    __shared__ int    s_cls[MAXT];
    __shared__ unsigned char s_validf[MAXT];
    __shared__ int    s_nvalid;
    __shared__ bool   s_last;

    const int b   = blockIdx.y;
    const int tid = threadIdx.x;
    const int bid = blockIdx.y * BLOCKS_PER_B + blockIdx.x;

    // ================= Phase 1a: issue per-cell global loads FIRST =========
    // (independent of smem; their latency overlaps the target setup below)
    float px1[CPT], px2[CPT], py1[CPT], py2[CPT], thrp[CPT], scv[CPT];
    int   keyi[CPT], off[CPT], owner[CPT];
    bool  kill[CPT];

    const int cell0 = blockIdx.x * CELLS_PER_BLK + tid;
    const int boff  = b * (NA*(5+NC)) * SPATIAL;

    float xr[CPT], yr[CPT], wr[CPT], hr[CPT], cr[CPT];
    #pragma unroll
    for (int k = 0; k < CPT; k++) {
        const int cell = cell0 + k * BLOCK;
        owner[k] = -1;
        if (cell < CELLS_PER_B) {
            const int a   = cell / SPATIAL;
            const int rem = cell - a * SPATIAL;
            off[k] = boff + a*(5+NC)*SPATIAL + rem;
            const float* bp = pred + off[k];
            xr[k] = bp[0];
            yr[k] = bp[SPATIAL];
            wr[k] = bp[2*SPATIAL];
            hr[k] = bp[3*SPATIAL];
            cr[k] = bp[4*SPATIAL];
            kill[k] = false;
        } else {
            off[k] = boff;
            xr[k]=yr[k]=wr[k]=hr[k]=cr[k]=0.f;
            kill[k] = true;     // forces zero contribution
        }
    }

    // ================= Phase 1b: target setup (warps 0-1 only) =============
    if (tid < MAXT) {
        const float* tp = tgt + (size_t)(b*MAXT + tid)*5;
        float cls = tp[0], cx = tp[1], cy = tp[2], wn = tp[3], hn = tp[4];
        s_validf[tid] = (cx != -1.0f);
        float gx = cx * WF, gy = cy * HF, gw = wn * WF, gh = hn * HF;
        float garea = gw * gh;
        int bn = 0; float best = -1.0f;
        #pragma unroll
        for (int n = 0; n < NA; n++) {
            float aw = c_anch[2*n], ah = c_anch[2*n+1];
            float inter = fminf(gw, aw) * fminf(gh, ah);
            float uni   = garea + aw*ah - inter;
            float iou   = (uni > 0.0f) ? inter/uni : 0.0f;  // exact: argmax ties
            if (iou > best) { best = iou; bn = n; }
        }
        int gi = min(max((int)gx, 0), WF-1);
        int gj = min(max((int)gy, 0), HF-1);
        int key = (bn*HF + gj)*WF + gi;
        s_tk[tid]  = make_float2(0.375f * garea, __int_as_float(key));
        s_tx[tid]  = gx - (float)gi;
        s_ty[tid]  = gy - (float)gj;
        float aw = c_anch[2*bn], ah = c_anch[2*bn+1];
        s_tw[tid]  = __logf(gw / aw);
        s_th[tid]  = __logf(gh / ah);
        s_cls[tid] = min(max((int)cls, 0), NC-1);
        s_box[tid] = make_float4(gx - gw*0.5f, gy - gh*0.5f,
                                 gx + gw*0.5f, gy + gh*0.5f);
        s_area[tid]= garea;
    }

    // ================= Phase 1c: per-cell geometry (no smem needed) ========
    #pragma unroll
    for (int k = 0; k < CPT; k++) {
        const int cell = cell0 + k * BLOCK;
        if (cell < CELLS_PER_B) {
            const int a   = cell / SPATIAL;
            const int rem = cell - a * SPATIAL;
            const int j   = rem / WF;
            const int i   = rem - j * WF;
            float sx = fsigmoid(xr[k]);
            float sy = fsigmoid(yr[k]);
            scv[k]   = fsigmoid(cr[k]);
            float bx = sx + (float)i;
            float by = sy + (float)j;
            float bw = __expf(wr[k]) * c_anch[2*a];
            float bh = __expf(hr[k]) * c_anch[2*a+1];
            px1[k] = bx - bw*0.5f; px2[k] = bx + bw*0.5f;
            py1[k] = by - bh*0.5f; py2[k] = by + bh*0.5f;
            thrp[k] = 0.375f * (bw * bh);
            keyi[k] = (a*HF + j)*WF + i;
        } else {
            px1[k]=px2[k]=py1[k]=py2[k]=0.f; thrp[k]=0.f; scv[k]=0.f;
            keyi[k] = -1;
        }
    }

    __syncthreads();
    if (tid == 0) {
        int n = 0;
        while (n < MAXT && s_validf[n]) n++;   // cumprod semantics
        s_nvalid = n;
    }
    __syncthreads();
    const int nv = s_nvalid;

    // ---- Hot loop: 2 LDS serve 4 independent cells (ILP hides latency) ----
    for (int t = 0; t < nv; t++) {
        float4 b4 = s_box[t];
        float2 tk = s_tk[t];
        int    tkey = __float_as_int(tk.y);
        #pragma unroll
        for (int k = 0; k < CPT; k++) {
            float cw  = fminf(px2[k], b4.z) - fmaxf(px1[k], b4.x);
            float chh = fminf(py2[k], b4.w) - fmaxf(py1[k], b4.y);
            float inter = cw * chh;
            kill[k] = kill[k] | ((fminf(cw, chh) > 0.0f) & (inter > thrp[k] + tk.x));
            if (tkey == keyi[k]) owner[k] = t;   // last valid target wins
        }
    }

    // ---- Epilogue per cell ----
    float contrib = 0.0f, ce = 0.0f;
    int   nobj = 0;
    int   tcv[CPT];
    bool  isobj[CPT];

    #pragma unroll
    for (int k = 0; k < CPT; k++) {
        isobj[k] = false; tcv[k] = 0;
        if (owner[k] >= 0) {
            const int o = owner[k];
            // rare path: recompute from raw preds still in registers
            float sx = fsigmoid(xr[k]);
            float sy = fsigmoid(yr[k]);
            const int a = keyi[k] / SPATIAL;
            float bw = __expf(wr[k]) * c_anch[2*a];
            float bh = __expf(hr[k]) * c_anch[2*a+1];
            float parea = bw * bh;
            float4 b4 = s_box[o];
            float cw  = fminf(px2[k], b4.z) - fmaxf(px1[k], b4.x);
            float chh = fminf(py2[k], b4.w) - fmaxf(py1[k], b4.y);
            float inter = (cw > 0.0f && chh > 0.0f) ? cw * chh : 0.0f;
            float uni   = parea + s_area[o] - inter;
            float tconf = (uni > 0.0f) ? __fdividef(inter, uni) : 0.0f;
            float dx = sx - s_tx[o];
            float dy = sy - s_ty[o];
            float dw = wr[k] - s_tw[o];
            float dh = hr[k] - s_th[o];
            contrib += dx*dx + dy*dy + dw*dw + dh*dh;     // COORD_SCALE = 1
            float dc = scv[k] - tconf;
            contrib += 5.0f * dc * dc;                     // OBJ_SCALE = 5
            tcv[k] = s_cls[o];
            isobj[k] = true;
            nobj++;
        } else if (!kill[k]) {
            contrib += scv[k] * scv[k];                    // NOOBJ, tconf = 0
        }
    }

    // ---- Warp-cooperative cross-entropy for obj cells (rare) ----
    const int lane = tid & 31;
    #pragma unroll
    for (int k = 0; k < CPT; k++) {
        unsigned int omask = __ballot_sync(FULLMASK, isobj[k]);
        while (omask) {
            int src = __ffs(omask) - 1;
            omask &= omask - 1;
            int offb = __shfl_sync(FULLMASK, off[k], src);
            int tcls = __shfl_sync(FULLMASK, tcv[k], src);
            const float* lg = pred + offb + 5*SPATIAL;

            float v0 = lg[(size_t)lane * SPATIAL];
            float v1 = lg[(size_t)(lane + 32) * SPATIAL];
            float v2 = (lane < NC - 64) ? lg[(size_t)(lane + 64) * SPATIAL] : -FLT_MAX;

            float m = fmaxf(fmaxf(v0, v1), v2);
            #pragma unroll
            for (int o = 16; o > 0; o >>= 1)
                m = fmaxf(m, __shfl_xor_sync(FULLMASK, m, o));

            float s = __expf(v0 - m) + __expf(v1 - m)
                    + ((lane < NC - 64) ? __expf(v2 - m) : 0.0f);
            #pragma unroll
            for (int o = 16; o > 0; o >>= 1)
                s += __shfl_xor_sync(FULLMASK, s, o);

            float tl_cand = (tcls < 32) ? v0 : ((tcls < 64) ? v1 : v2);
            float tl = __shfl_sync(FULLMASK, tl_cand, tcls & 31);

            float ce_val = (m + __logf(s)) - tl;
            if (lane == src) ce += ce_val;
        }
    }

    // ---- Block reduction ----
    float r_main = contrib, r_ce = ce; int r_no = nobj;
    #pragma unroll
    for (int o = 16; o > 0; o >>= 1) {
        r_main += __shfl_down_sync(FULLMASK, r_main, o);
        r_ce   += __shfl_down_sync(FULLMASK, r_ce, o);
        r_no   += __shfl_down_sync(FULLMASK, r_no, o);
    }
    __shared__ float w0[BLOCK/32], w1[BLOCK/32];
    __shared__ int   w2[BLOCK/32];
    const int wid = tid >> 5;
    if (lane == 0) { w0[wid] = r_main; w1[wid] = r_ce; w2[wid] = r_no; }
    __syncthreads();
    if (tid == 0) {
        float a0 = 0.f, a1 = 0.f; int a2 = 0;
        #pragma unroll
        for (int k = 0; k < BLOCK/32; k++) { a0 += w0[k]; a1 += w1[k]; a2 += w2[k]; }
        g_part_main[bid] = a0;
        g_part_ce[bid]   = a1;
        g_part_nobj[bid] = a2;
        __threadfence();
        unsigned int t = atomicAdd(&g_ticket, 1u);
        s_last = (t == NBLK - 1);
    }
    __syncthreads();

    // ---- Last block: reduce partials in double, write result, reset ticket ----
    if (s_last) {
        __threadfence();
        double dm = 0.0, dc = 0.0; int dn = 0;
        for (int k = tid; k < NBLK; k += BLOCK) {
            dm += (double)g_part_main[k];
            dc += (double)g_part_ce[k];
            dn += g_part_nobj[k];
        }
        #pragma unroll
        for (int o = 16; o > 0; o >>= 1) {
            dm += __shfl_down_sync(FULLMASK, dm, o);
            dc += __shfl_down_sync(FULLMASK, dc, o);
            dn += __shfl_down_sync(FULLMASK, dn, o);
        }
        __shared__ double d0[BLOCK/32], d1[BLOCK/32];
        __shared__ int    d2[BLOCK/32];
        if (lane == 0) { d0[wid] = dm; d1[wid] = dc; d2[wid] = dn; }
        __syncthreads();
        if (tid == 0) {
            double sm = 0.0, scc = 0.0; int sn = 0;
            #pragma unroll
            for (int k = 0; k < BLOCK/32; k++) { sm += d0[k]; scc += d1[k]; sn += d2[k]; }
            double n = (double)sn;
            if (n < 1.0) n = 1.0;
            out[0] = (float)(sm + scc / n);
            g_ticket = 0;   // reset for next graph replay
        }
    }
}

extern "C" void kernel_launch(void* const* d_in, const int* in_sizes, int n_in,
                              void* d_out, int out_size) {
    const float* pred = (const float*)d_in[0];
    const float* tgt  = (const float*)d_in[1];
    dim3 grid(BLOCKS_PER_B, BATCH);
    yolo_k<<<grid, BLOCK>>>(pred, tgt, (float*)d_out);
}

// round 14
// speedup vs baseline: 1.9629x; 1.1062x over previous
#include <cuda_runtime.h>
#include <math.h>
#include <float.h>

#define NA 5
#define NC 80
#define MAXT 50
#define HF 38
#define WF 38
#define SPATIAL (HF*WF)            // 1444
#define CELLS_PER_B (NA*SPATIAL)   // 7220
#define BLOCK 128
#define CPT 2                      // cells per thread
#define CELLS_PER_BLK (BLOCK*CPT)  // 256
#define BLOCKS_PER_B ((CELLS_PER_B + CELLS_PER_BLK - 1)/CELLS_PER_BLK)  // 29
#define BATCH 64
#define NBLK (BLOCKS_PER_B*BATCH)  // 1856
#define FULLMASK 0xFFFFFFFFu

__constant__ float c_anch[NA*2] = {
    0.57273f, 0.677385f,
    1.87446f, 2.06253f,
    3.33843f, 5.47434f,
    7.88282f, 3.52778f,
    9.77052f, 9.16828f
};

// Global accumulators (zero-init; last block resets them each launch)
__device__ double       g_main;
__device__ double       g_ce;
__device__ int          g_nobj;
__device__ unsigned int g_ticket;

__device__ __forceinline__ float fsigmoid(float v) {
    return __fdividef(1.0f, 1.0f + __expf(-v));
}

__global__ void __launch_bounds__(BLOCK, 9) yolo_k(const float* __restrict__ pred,
                                                   const float* __restrict__ tgt,
                                                   float* __restrict__ out) {
    __shared__ float4 s_box[MAXT];         // x1,y1,x2,y2
    __shared__ float2 s_tk[MAXT];          // .x = 0.375*garea, .y = key bits
    __shared__ float  s_area[MAXT];
    __shared__ float  s_tx[MAXT], s_ty[MAXT], s_tw[MAXT], s_th[MAXT];
    __shared__ int    s_cls[MAXT];
    __shared__ unsigned int s_vm[2];       // validity bitmask (cumulative via ffs)

    const int b   = blockIdx.y;
    const int tid = threadIdx.x;

    // ===== Phase 1a: issue per-cell global loads first (overlap target setup)
    float px1[CPT], px2[CPT], py1[CPT], py2[CPT], thrp[CPT], scv[CPT];
    int   keyi[CPT], off[CPT], owner[CPT];
    bool  kill[CPT];
    float xr[CPT], yr[CPT], wr[CPT], hr[CPT], cr[CPT];

    const int cell0 = blockIdx.x * CELLS_PER_BLK + tid;
    const int boff  = b * (NA*(5+NC)) * SPATIAL;

    #pragma unroll
    for (int k = 0; k < CPT; k++) {
        const int cell = cell0 + k * BLOCK;
        owner[k] = -1;
        if (cell < CELLS_PER_B) {
            const int a   = cell / SPATIAL;
            const int rem = cell - a * SPATIAL;
            off[k] = boff + a*(5+NC)*SPATIAL + rem;
            const float* bp = pred + off[k];
            xr[k] = bp[0];
            yr[k] = bp[SPATIAL];
            wr[k] = bp[2*SPATIAL];
            hr[k] = bp[3*SPATIAL];
            cr[k] = bp[4*SPATIAL];
            kill[k] = false;
        } else {
            off[k] = boff;
            xr[k]=yr[k]=wr[k]=hr[k]=cr[k]=0.f;
            kill[k] = true;     // forces zero contribution
        }
    }

    // ===== Phase 1b: target setup (warps 0-1), validity via ballot ==========
    bool validt = false;
    if (tid < MAXT) {
        const float* tp = tgt + (size_t)(b*MAXT + tid)*5;
        float cls = tp[0], cx = tp[1], cy = tp[2], wn = tp[3], hn = tp[4];
        validt = (cx != -1.0f);
        float gx = cx * WF, gy = cy * HF, gw = wn * WF, gh = hn * HF;
        float garea = gw * gh;
        int bn = 0; float best = -1.0f;
        #pragma unroll
        for (int n = 0; n < NA; n++) {
            float aw = c_anch[2*n], ah = c_anch[2*n+1];
            float inter = fminf(gw, aw) * fminf(gh, ah);
            float uni   = garea + aw*ah - inter;
            float iou   = (uni > 0.0f) ? inter/uni : 0.0f;  // exact: argmax ties
            if (iou > best) { best = iou; bn = n; }
        }
        int gi = min(max((int)gx, 0), WF-1);
        int gj = min(max((int)gy, 0), HF-1);
        int key = (bn*HF + gj)*WF + gi;
        s_tk[tid]  = make_float2(0.375f * garea, __int_as_float(key));
        s_tx[tid]  = gx - (float)gi;
        s_ty[tid]  = gy - (float)gj;
        float aw = c_anch[2*bn], ah = c_anch[2*bn+1];
        s_tw[tid]  = __logf(gw / aw);
        s_th[tid]  = __logf(gh / ah);
        s_cls[tid] = min(max((int)cls, 0), NC-1);
        s_box[tid] = make_float4(gx - gw*0.5f, gy - gh*0.5f,
                                 gx + gw*0.5f, gy + gh*0.5f);
        s_area[tid]= garea;
    }
    if (tid < 64) {
        unsigned int m = __ballot_sync(FULLMASK, validt);
        if ((tid & 31) == 0) s_vm[tid >> 5] = m;
    }

    // ===== Phase 1c: per-cell geometry (regs only) =========================
    #pragma unroll
    for (int k = 0; k < CPT; k++) {
        const int cell = cell0 + k * BLOCK;
        if (cell < CELLS_PER_B) {
            const int a   = cell / SPATIAL;
            const int rem = cell - a * SPATIAL;
            const int j   = rem / WF;
            const int i   = rem - j * WF;
            float sx = fsigmoid(xr[k]);
            float sy = fsigmoid(yr[k]);
            scv[k]   = fsigmoid(cr[k]);
            float bx = sx + (float)i;
            float by = sy + (float)j;
            float bw = __expf(wr[k]) * c_anch[2*a];
            float bh = __expf(hr[k]) * c_anch[2*a+1];
            px1[k] = bx - bw*0.5f; px2[k] = bx + bw*0.5f;
            py1[k] = by - bh*0.5f; py2[k] = by + bh*0.5f;
            thrp[k] = 0.375f * (bw * bh);
            keyi[k] = (a*HF + j)*WF + i;
        } else {
            px1[k]=px2[k]=py1[k]=py2[k]=0.f; thrp[k]=0.f; scv[k]=0.f;
            keyi[k] = -1;
        }
    }
    // raw xr..cr intentionally dead here (rare owner path reloads from L2)

    __syncthreads();
    unsigned long long vm = (unsigned long long)s_vm[0]
                          | ((unsigned long long)s_vm[1] << 32);
    const int nv = min((int)(__ffsll(~vm) - 1), MAXT);   // first invalid = count

    // ---- Hot loop: 2 LDS serve 2 independent cells ----
    for (int t = 0; t < nv; t++) {
        float4 b4 = s_box[t];
        float2 tk = s_tk[t];
        int    tkey = __float_as_int(tk.y);
        #pragma unroll
        for (int k = 0; k < CPT; k++) {
            float cw  = fminf(px2[k], b4.z) - fmaxf(px1[k], b4.x);
            float chh = fminf(py2[k], b4.w) - fmaxf(py1[k], b4.y);
            float inter = fmaxf(cw, 0.0f) * fmaxf(chh, 0.0f);
            kill[k] = kill[k] | (inter > thrp[k] + tk.x);
            if (tkey == keyi[k]) owner[k] = t;   // last valid target wins
        }
    }

    // ---- Epilogue per cell ----
    float contrib = 0.0f, ce = 0.0f;
    int   nobj = 0;
    int   tcv[CPT];
    bool  isobj[CPT];

    #pragma unroll
    for (int k = 0; k < CPT; k++) {
        isobj[k] = false; tcv[k] = 0;
        if (owner[k] >= 0) {
            const int o = owner[k];
            // rare path: reload raw preds (L2-hot) and recompute exactly
            const float* bp = pred + off[k];
            float x  = bp[0];
            float yv = bp[SPATIAL];
            float w  = bp[2*SPATIAL];
            float h  = bp[3*SPATIAL];
            float sx = fsigmoid(x);
            float sy = fsigmoid(yv);
            const int a = keyi[k] / SPATIAL;
            float bw = __expf(w) * c_anch[2*a];
            float bh = __expf(h) * c_anch[2*a+1];
            float parea = bw * bh;
            float4 b4 = s_box[o];
            float cw  = fminf(px2[k], b4.z) - fmaxf(px1[k], b4.x);
            float chh = fminf(py2[k], b4.w) - fmaxf(py1[k], b4.y);
            float inter = (cw > 0.0f && chh > 0.0f) ? cw * chh : 0.0f;
            float uni   = parea + s_area[o] - inter;
            float tconf = (uni > 0.0f) ? __fdividef(inter, uni) : 0.0f;
            float dx = sx - s_tx[o];
            float dy = sy - s_ty[o];
            float dw = w  - s_tw[o];
            float dh = h  - s_th[o];
            contrib += dx*dx + dy*dy + dw*dw + dh*dh;     // COORD_SCALE = 1
            float dc = scv[k] - tconf;
            contrib += 5.0f * dc * dc;                     // OBJ_SCALE = 5
            tcv[k] = s_cls[o];
            isobj[k] = true;
            nobj++;
        } else if (!kill[k]) {
            contrib += scv[k] * scv[k];                    // NOOBJ, tconf = 0
        }
    }

    // ---- Warp-cooperative cross-entropy for obj cells (rare) ----
    const int lane = tid & 31;
    #pragma unroll
    for (int k = 0; k < CPT; k++) {
        unsigned int omask = __ballot_sync(FULLMASK, isobj[k]);
        while (omask) {
            int src = __ffs(omask) - 1;
            omask &= omask - 1;
            int offb = __shfl_sync(FULLMASK, off[k], src);
            int tcls = __shfl_sync(FULLMASK, tcv[k], src);
            const float* lg = pred + offb + 5*SPATIAL;

            float v0 = lg[(size_t)lane * SPATIAL];
            float v1 = lg[(size_t)(lane + 32) * SPATIAL];
            float v2 = (lane < NC - 64) ? lg[(size_t)(lane + 64) * SPATIAL] : -FLT_MAX;

            float m = fmaxf(fmaxf(v0, v1), v2);
            #pragma unroll
            for (int o = 16; o > 0; o >>= 1)
                m = fmaxf(m, __shfl_xor_sync(FULLMASK, m, o));

            float s = __expf(v0 - m) + __expf(v1 - m)
                    + ((lane < NC - 64) ? __expf(v2 - m) : 0.0f);
            #pragma unroll
            for (int o = 16; o > 0; o >>= 1)
                s += __shfl_xor_sync(FULLMASK, s, o);

            float tl_cand = (tcls < 32) ? v0 : ((tcls < 64) ? v1 : v2);
            float tl = __shfl_sync(FULLMASK, tl_cand, tcls & 31);

            float ce_val = (m + __logf(s)) - tl;
            if (lane == src) ce += ce_val;
        }
    }

    // ---- Block reduction -> global double atomics (no partial arrays) ----
    float r_main = contrib, r_ce = ce; int r_no = nobj;
    #pragma unroll
    for (int o = 16; o > 0; o >>= 1) {
        r_main += __shfl_down_sync(FULLMASK, r_main, o);
        r_ce   += __shfl_down_sync(FULLMASK, r_ce, o);
        r_no   += __shfl_down_sync(FULLMASK, r_no, o);
    }
    __shared__ float w0[BLOCK/32], w1[BLOCK/32];
    __shared__ int   w2[BLOCK/32];
    const int wid = tid >> 5;
    if (lane == 0) { w0[wid] = r_main; w1[wid] = r_ce; w2[wid] = r_no; }
    __syncthreads();
    if (tid == 0) {
        float a0 = 0.f, a1 = 0.f; int a2 = 0;
        #pragma unroll
        for (int k = 0; k < BLOCK/32; k++) { a0 += w0[k]; a1 += w1[k]; a2 += w2[k]; }
        atomicAdd(&g_main, (double)a0);
        if (a1 != 0.0f) atomicAdd(&g_ce, (double)a1);
        if (a2)         atomicAdd(&g_nobj, a2);
        __threadfence();
        unsigned int t = atomicAdd(&g_ticket, 1u);
        if (t == NBLK - 1) {
            // all other blocks' adds are fenced before their ticket increments
            __threadfence();
            double sm = g_main, scc = g_ce;
            double n = (double)g_nobj;
            if (n < 1.0) n = 1.0;
            out[0] = (float)(sm + scc / n);
            g_main = 0.0; g_ce = 0.0; g_nobj = 0;    // reset for next replay
            __threadfence();
            g_ticket = 0;
        }
    }
}

extern "C" void kernel_launch(void* const* d_in, const int* in_sizes, int n_in,
                              void* d_out, int out_size) {
    const float* pred = (const float*)d_in[0];
    const float* tgt  = (const float*)d_in[1];
    dim3 grid(BLOCKS_PER_B, BATCH);
    yolo_k<<<grid, BLOCK>>>(pred, tgt, (float*)d_out);
}

// round 16
// speedup vs baseline: 2.1716x; 1.1063x over previous
#include <cuda_runtime.h>
#include <math.h>
#include <float.h>

#define NA 5
#define NC 80
#define MAXT 50
#define MAXTP (MAXT + 4)           // padded so unroll-4 can overread safely
#define HF 38
#define WF 38
#define SPATIAL (HF*WF)            // 1444
#define CELLS_PER_B (NA*SPATIAL)   // 7220
#define BLOCK 128
#define CPT 2                      // cells per thread
#define CELLS_PER_BLK (BLOCK*CPT)  // 256
#define BLOCKS_PER_B ((CELLS_PER_B + CELLS_PER_BLK - 1)/CELLS_PER_BLK)  // 29
#define BATCH 64
#define NBLK (BLOCKS_PER_B*BATCH)  // 1856
#define FULLMASK 0xFFFFFFFFu

__constant__ float c_anch[NA*2] = {
    0.57273f, 0.677385f,
    1.87446f, 2.06253f,
    3.33843f, 5.47434f,
    7.88282f, 3.52778f,
    9.77052f, 9.16828f
};

// Global accumulators (zero-init; last block resets them each launch)
__device__ double       g_main;
__device__ double       g_ce;
__device__ int          g_nobj;
__device__ unsigned int g_ticket;

__device__ __forceinline__ float fsigmoid(float v) {
    return __fdividef(1.0f, 1.0f + __expf(-v));
}

__global__ void __launch_bounds__(BLOCK, 12) yolo_k(const float* __restrict__ pred,
                                                    const float* __restrict__ tgt,
                                                    float* __restrict__ out) {
    __shared__ float4 s_box[MAXTP];        // x1,y1,x2,y2  (padded for unroll)
    __shared__ float2 s_tk[MAXTP];         // .x = 0.375*garea, .y = key bits
    __shared__ float  s_area[MAXT];
    __shared__ float  s_tx[MAXT], s_ty[MAXT], s_tw[MAXT], s_th[MAXT];
    __shared__ int    s_cls[MAXT];
    __shared__ unsigned int s_vm[2];       // validity bitmask

    const int b   = blockIdx.y;
    const int tid = threadIdx.x;

    // Zero the pad entries so unrolled overreads are benign (no NaN surprises)
    if (tid < 4) {
        s_box[MAXT + tid] = make_float4(0.f, 0.f, 0.f, 0.f);
        s_tk[MAXT + tid]  = make_float2(1e30f, __int_as_float(-2));
    }

    // ===== Phase 1a: issue per-cell global loads first =====================
    float px1[CPT], px2[CPT], py1[CPT], py2[CPT], thrp[CPT], scv[CPT];
    int   keyi[CPT], off[CPT], owner[CPT];
    bool  kill[CPT];
    float xr[CPT], yr[CPT], wr[CPT], hr[CPT], cr[CPT];

    const int cell0 = blockIdx.x * CELLS_PER_BLK + tid;
    const int boff  = b * (NA*(5+NC)) * SPATIAL;

    #pragma unroll
    for (int k = 0; k < CPT; k++) {
        const int cell = cell0 + k * BLOCK;
        owner[k] = -1;
        if (cell < CELLS_PER_B) {
            const int a   = cell / SPATIAL;
            const int rem = cell - a * SPATIAL;
            off[k] = boff + a*(5+NC)*SPATIAL + rem;
            const float* bp = pred + off[k];
            xr[k] = bp[0];
            yr[k] = bp[SPATIAL];
            wr[k] = bp[2*SPATIAL];
            hr[k] = bp[3*SPATIAL];
            cr[k] = bp[4*SPATIAL];
            kill[k] = false;
        } else {
            off[k] = boff;
            xr[k]=yr[k]=wr[k]=hr[k]=cr[k]=0.f;
            kill[k] = true;     // forces zero contribution
        }
    }

    // ===== Phase 1b: target setup (warps 0-1), validity via ballot =========
    bool validt = false;
    if (tid < MAXT) {
        const float* tp = tgt + (size_t)(b*MAXT + tid)*5;
        float cls = tp[0], cx = tp[1], cy = tp[2], wn = tp[3], hn = tp[4];
        validt = (cx != -1.0f);
        float gx = cx * WF, gy = cy * HF, gw = wn * WF, gh = hn * HF;
        float garea = gw * gh;
        int bn = 0; float best = -1.0f;
        #pragma unroll
        for (int n = 0; n < NA; n++) {
            float aw = c_anch[2*n], ah = c_anch[2*n+1];
            float inter = fminf(gw, aw) * fminf(gh, ah);
            float uni   = garea + aw*ah - inter;
            float iou   = (uni > 0.0f) ? inter/uni : 0.0f;  // exact: argmax ties
            if (iou > best) { best = iou; bn = n; }
        }
        int gi = min(max((int)gx, 0), WF-1);
        int gj = min(max((int)gy, 0), HF-1);
        int key = (bn*HF + gj)*WF + gi;
        s_tk[tid]  = make_float2(0.375f * garea, __int_as_float(key));
        s_tx[tid]  = gx - (float)gi;
        s_ty[tid]  = gy - (float)gj;
        float aw = c_anch[2*bn], ah = c_anch[2*bn+1];
        s_tw[tid]  = __logf(gw / aw);
        s_th[tid]  = __logf(gh / ah);
        s_cls[tid] = min(max((int)cls, 0), NC-1);
        s_box[tid] = make_float4(gx - gw*0.5f, gy - gh*0.5f,
                                 gx + gw*0.5f, gy + gh*0.5f);
        s_area[tid]= garea;
    }
    if (tid < 64) {
        unsigned int m = __ballot_sync(FULLMASK, validt);
        if ((tid & 31) == 0) s_vm[tid >> 5] = m;
    }

    // ===== Phase 1c: per-cell geometry (regs only) =========================
    #pragma unroll
    for (int k = 0; k < CPT; k++) {
        const int cell = cell0 + k * BLOCK;
        if (cell < CELLS_PER_B) {
            const int a   = cell / SPATIAL;
            const int rem = cell - a * SPATIAL;
            const int j   = rem / WF;
            const int i   = rem - j * WF;
            float sx = fsigmoid(xr[k]);
            float sy = fsigmoid(yr[k]);
            scv[k]   = fsigmoid(cr[k]);
            float bx = sx + (float)i;
            float by = sy + (float)j;
            float bw = __expf(wr[k]) * c_anch[2*a];
            float bh = __expf(hr[k]) * c_anch[2*a+1];
            px1[k] = bx - bw*0.5f; px2[k] = bx + bw*0.5f;
            py1[k] = by - bh*0.5f; py2[k] = by + bh*0.5f;
            thrp[k] = 0.375f * (bw * bh);
            keyi[k] = (a*HF + j)*WF + i;
        } else {
            px1[k]=px2[k]=py1[k]=py2[k]=0.f; thrp[k]=0.f; scv[k]=0.f;
            keyi[k] = -1;
        }
    }
    // raw xr..cr dead here (rare owner path reloads from L2)

    __syncthreads();
    unsigned long long vm = (unsigned long long)s_vm[0]
                          | ((unsigned long long)s_vm[1] << 32);
    const int nv = min((int)(__ffsll(~vm) - 1), MAXT);   // first invalid = count

    // ---- Hot loop, unroll 4: 8 LDS batched per 4 targets, latency covered --
    #pragma unroll 4
    for (int t = 0; t < nv; t++) {
        float4 b4 = s_box[t];
        float2 tk = s_tk[t];
        int    tkey = __float_as_int(tk.y);
        #pragma unroll
        for (int k = 0; k < CPT; k++) {
            float cw  = fminf(px2[k], b4.z) - fmaxf(px1[k], b4.x);
            float chh = fminf(py2[k], b4.w) - fmaxf(py1[k], b4.y);
            float inter = fmaxf(cw, 0.0f) * fmaxf(chh, 0.0f);
            kill[k] = kill[k] | (inter > thrp[k] + tk.x);
            if (tkey == keyi[k]) owner[k] = t;   // last valid target wins
        }
    }

    // ---- Epilogue per cell ----
    float contrib = 0.0f, ce = 0.0f;
    int   nobj = 0;
    int   tcv[CPT];
    bool  isobj[CPT];

    #pragma unroll
    for (int k = 0; k < CPT; k++) {
        isobj[k] = false; tcv[k] = 0;
        if (owner[k] >= 0) {
            const int o = owner[k];
            // rare path: reload raw preds (L2-hot) and recompute exactly
            const float* bp = pred + off[k];
            float x  = bp[0];
            float yv = bp[SPATIAL];
            float w  = bp[2*SPATIAL];
            float h  = bp[3*SPATIAL];
            float sx = fsigmoid(x);
            float sy = fsigmoid(yv);
            const int a = keyi[k] / SPATIAL;
            float bw = __expf(w) * c_anch[2*a];
            float bh = __expf(h) * c_anch[2*a+1];
            float parea = bw * bh;
            float4 b4 = s_box[o];
            float cw  = fminf(px2[k], b4.z) - fmaxf(px1[k], b4.x);
            float chh = fminf(py2[k], b4.w) - fmaxf(py1[k], b4.y);
            float inter = (cw > 0.0f && chh > 0.0f) ? cw * chh : 0.0f;
            float uni   = parea + s_area[o] - inter;
            float tconf = (uni > 0.0f) ? __fdividef(inter, uni) : 0.0f;
            float dx = sx - s_tx[o];
            float dy = sy - s_ty[o];
            float dw = w  - s_tw[o];
            float dh = h  - s_th[o];
            contrib += dx*dx + dy*dy + dw*dw + dh*dh;     // COORD_SCALE = 1
            float dc = scv[k] - tconf;
            contrib += 5.0f * dc * dc;                     // OBJ_SCALE = 5
            tcv[k] = s_cls[o];
            isobj[k] = true;
            nobj++;
        } else if (!kill[k]) {
            contrib += scv[k] * scv[k];                    // NOOBJ, tconf = 0
        }
    }

    // ---- Warp-cooperative cross-entropy for obj cells (rare) ----
    const int lane = tid & 31;
    #pragma unroll
    for (int k = 0; k < CPT; k++) {
        unsigned int omask = __ballot_sync(FULLMASK, isobj[k]);
        while (omask) {
            int src = __ffs(omask) - 1;
            omask &= omask - 1;
            int offb = __shfl_sync(FULLMASK, off[k], src);
            int tcls = __shfl_sync(FULLMASK, tcv[k], src);
            const float* lg = pred + offb + 5*SPATIAL;

            float v0 = lg[(size_t)lane * SPATIAL];
            float v1 = lg[(size_t)(lane + 32) * SPATIAL];
            float v2 = (lane < NC - 64) ? lg[(size_t)(lane + 64) * SPATIAL] : -FLT_MAX;

            float m = fmaxf(fmaxf(v0, v1), v2);
            #pragma unroll
            for (int o = 16; o > 0; o >>= 1)
                m = fmaxf(m, __shfl_xor_sync(FULLMASK, m, o));

            float s = __expf(v0 - m) + __expf(v1 - m)
                    + ((lane < NC - 64) ? __expf(v2 - m) : 0.0f);
            #pragma unroll
            for (int o = 16; o > 0; o >>= 1)
                s += __shfl_xor_sync(FULLMASK, s, o);

            float tl_cand = (tcls < 32) ? v0 : ((tcls < 64) ? v1 : v2);
            float tl = __shfl_sync(FULLMASK, tl_cand, tcls & 31);

            float ce_val = (m + __logf(s)) - tl;
            if (lane == src) ce += ce_val;
        }
    }

    // ---- Block reduction -> global double atomics ----
    float r_main = contrib, r_ce = ce; int r_no = nobj;
    #pragma unroll
    for (int o = 16; o > 0; o >>= 1) {
        r_main += __shfl_down_sync(FULLMASK, r_main, o);
        r_ce   += __shfl_down_sync(FULLMASK, r_ce, o);
        r_no   += __shfl_down_sync(FULLMASK, r_no, o);
    }
    __shared__ float w0[BLOCK/32], w1[BLOCK/32];
    __shared__ int   w2[BLOCK/32];
    const int wid = tid >> 5;
    if (lane == 0) { w0[wid] = r_main; w1[wid] = r_ce; w2[wid] = r_no; }
    __syncthreads();
    if (tid == 0) {
        float a0 = 0.f, a1 = 0.f; int a2 = 0;
        #pragma unroll
        for (int k = 0; k < BLOCK/32; k++) { a0 += w0[k]; a1 += w1[k]; a2 += w2[k]; }
        atomicAdd(&g_main, (double)a0);
        if (a1 != 0.0f) atomicAdd(&g_ce, (double)a1);
        if (a2)         atomicAdd(&g_nobj, a2);
        __threadfence();
        unsigned int t = atomicAdd(&g_ticket, 1u);
        if (t == NBLK - 1) {
            __threadfence();
            double sm = g_main, scc = g_ce;
            double n = (double)g_nobj;
            if (n < 1.0) n = 1.0;
            out[0] = (float)(sm + scc / n);
            g_main = 0.0; g_ce = 0.0; g_nobj = 0;    // reset for next replay
            __threadfence();
            g_ticket = 0;
        }
    }
}

extern "C" void kernel_launch(void* const* d_in, const int* in_sizes, int n_in,
                              void* d_out, int out_size) {
    const float* pred = (const float*)d_in[0];
    const float* tgt  = (const float*)d_in[1];
    dim3 grid(BLOCKS_PER_B, BATCH);
    yolo_k<<<grid, BLOCK>>>(pred, tgt, (float*)d_out);
}

// round 17
// speedup vs baseline: 2.2558x; 1.0388x over previous
#include <cuda_runtime.h>
#include <math.h>
#include <float.h>

#define NA 5
#define NC 80
#define MAXT 50
#define MAXTP (MAXT + 4)           // padded so unroll-4 can overread safely
#define HF 38
#define WF 38
#define SPATIAL (HF*WF)            // 1444
#define CELLS_PER_B (NA*SPATIAL)   // 7220
#define BLOCK 128
#define CPT 2                      // cells per thread
#define CELLS_PER_BLK (BLOCK*CPT)  // 256
#define BLOCKS_PER_B ((CELLS_PER_B + CELLS_PER_BLK - 1)/CELLS_PER_BLK)  // 29
#define BATCH 64
#define NBLK (BLOCKS_PER_B*BATCH)  // 1856
#define FULLMASK 0xFFFFFFFFu

__constant__ float c_anch[NA*2] = {
    0.57273f, 0.677385f,
    1.87446f, 2.06253f,
    3.33843f, 5.47434f,
    7.88282f, 3.52778f,
    9.77052f, 9.16828f
};

// Global accumulators (zero-init; last block resets them each launch)
__device__ double       g_main;
__device__ double       g_ce;
__device__ int          g_nobj;
__device__ unsigned int g_ticket;

__device__ __forceinline__ float fsigmoid(float v) {
    return __fdividef(1.0f, 1.0f + __expf(-v));
}

__global__ void __launch_bounds__(BLOCK, 12) yolo_k(const float* __restrict__ pred,
                                                    const float* __restrict__ tgt,
                                                    float* __restrict__ out) {
    // Original (uncompacted) per-target data, used by the rare epilogue
    __shared__ float4 s_box[MAXT];
    __shared__ float  s_area[MAXT];
    __shared__ float  s_tx[MAXT], s_ty[MAXT], s_tw[MAXT], s_th[MAXT];
    __shared__ int    s_cls[MAXT];
    // Row-filtered compacted copies for the hot loop (order preserved)
    __shared__ float4 s_cbox[MAXTP];
    __shared__ float2 s_ctk[MAXTP];        // .x = 0.375*garea, .y = key bits
    __shared__ int    s_cidx[MAXTP];       // original target index
    __shared__ unsigned int s_vm[2];       // validity ballot
    __shared__ unsigned int s_pm[2];       // row-pass ballot

    const int b   = blockIdx.y;
    const int tid = threadIdx.x;

    // ===== Block's covered row range (for the y-prune) =====================
    const int c0   = blockIdx.x * CELLS_PER_BLK;
    const int cend = min(c0 + CELLS_PER_BLK - 1, CELLS_PER_B - 1);
    int r0, r1;
    {
        const int a0 = c0 / SPATIAL, a1 = cend / SPATIAL;
        if (a0 != a1) { r0 = 0; r1 = HF - 1; }               // anchor-wrap: no prune
        else { r0 = (c0 - a0*SPATIAL) / WF; r1 = (cend - a0*SPATIAL) / WF; }
    }
    const float r0f = (float)r0, r1f = (float)r1;

    // ===== Phase 1a: issue per-cell global loads first =====================
    float px1[CPT], px2[CPT], py1[CPT], py2[CPT], thrp[CPT], scv[CPT];
    int   keyi[CPT], off[CPT], owner[CPT];
    bool  kill[CPT];
    float xr[CPT], yr[CPT], wr[CPT], hr[CPT], cr[CPT];

    const int cell0 = c0 + tid;
    const int boff  = b * (NA*(5+NC)) * SPATIAL;

    #pragma unroll
    for (int k = 0; k < CPT; k++) {
        const int cell = cell0 + k * BLOCK;
        owner[k] = -1;
        if (cell < CELLS_PER_B) {
            const int a   = cell / SPATIAL;
            const int rem = cell - a * SPATIAL;
            off[k] = boff + a*(5+NC)*SPATIAL + rem;
            const float* bp = pred + off[k];
            xr[k] = bp[0];
            yr[k] = bp[SPATIAL];
            wr[k] = bp[2*SPATIAL];
            hr[k] = bp[3*SPATIAL];
            cr[k] = bp[4*SPATIAL];
            kill[k] = false;
        } else {
            off[k] = boff;
            xr[k]=yr[k]=wr[k]=hr[k]=cr[k]=0.f;
            kill[k] = true;     // forces zero contribution
        }
    }

    // ===== Phase 1b: target setup (warps 0-1) + validity/pass ballots ======
    bool validt = false, passt = false;
    float  my_thr = 0.f; int my_key = -3;
    float4 my_box = make_float4(0.f,0.f,0.f,0.f);
    if (tid < MAXT) {
        const float* tp = tgt + (size_t)(b*MAXT + tid)*5;
        float cls = tp[0], cx = tp[1], cy = tp[2], wn = tp[3], hn = tp[4];
        validt = (cx != -1.0f);
        float gx = cx * WF, gy = cy * HF, gw = wn * WF, gh = hn * HF;
        float garea = gw * gh;
        int bn = 0; float best = -1.0f;
        #pragma unroll
        for (int n = 0; n < NA; n++) {
            float aw = c_anch[2*n], ah = c_anch[2*n+1];
            float inter = fminf(gw, aw) * fminf(gh, ah);
            float uni   = garea + aw*ah - inter;
            float iou   = (uni > 0.0f) ? inter/uni : 0.0f;  // exact: argmax ties
            if (iou > best) { best = iou; bn = n; }
        }
        int gi = min(max((int)gx, 0), WF-1);
        int gj = min(max((int)gy, 0), HF-1);
        my_key = (bn*HF + gj)*WF + gi;
        s_tx[tid]  = gx - (float)gi;
        s_ty[tid]  = gy - (float)gj;
        float aw = c_anch[2*bn], ah = c_anch[2*bn+1];
        s_tw[tid]  = __logf(gw / aw);
        s_th[tid]  = __logf(gh / ah);
        s_cls[tid] = min(max((int)cls, 0), NC-1);
        my_box = make_float4(gx - gw*0.5f, gy - gh*0.5f,
                             gx + gw*0.5f, gy + gh*0.5f);
        my_thr = 0.375f * garea;
        s_box[tid] = my_box;
        s_area[tid]= garea;
        // y-prune: kill possible only in rows (gy-0.534gh-1, gy+0.534gh);
        // conservative margins, plus explicit owner-row inclusion.
        float jlo = gy - 0.54f*gh - 1.05f;
        float jhi = gy + 0.54f*gh + 0.05f;
        passt = (jhi >= r0f && jlo <= r1f) || (gj >= r0 && gj <= r1);
    }
    if (tid < 64) {
        unsigned int vmm = __ballot_sync(FULLMASK, validt);
        unsigned int pmm = __ballot_sync(FULLMASK, passt);
        if ((tid & 31) == 0) { s_vm[tid >> 5] = vmm; s_pm[tid >> 5] = pmm; }
    }

    // ===== Phase 1c: per-cell geometry (regs only) =========================
    #pragma unroll
    for (int k = 0; k < CPT; k++) {
        const int cell = cell0 + k * BLOCK;
        if (cell < CELLS_PER_B) {
            const int a   = cell / SPATIAL;
            const int rem = cell - a * SPATIAL;
            const int j   = rem / WF;
            const int i   = rem - j * WF;
            float sx = fsigmoid(xr[k]);
            float sy = fsigmoid(yr[k]);
            scv[k]   = fsigmoid(cr[k]);
            float bx = sx + (float)i;
            float by = sy + (float)j;
            float bw = __expf(wr[k]) * c_anch[2*a];
            float bh = __expf(hr[k]) * c_anch[2*a+1];
            px1[k] = bx - bw*0.5f; px2[k] = bx + bw*0.5f;
            py1[k] = by - bh*0.5f; py2[k] = by + bh*0.5f;
            thrp[k] = 0.375f * (bw * bh);
            keyi[k] = (a*HF + j)*WF + i;
        } else {
            px1[k]=px2[k]=py1[k]=py2[k]=0.f; thrp[k]=0.f; scv[k]=0.f;
            keyi[k] = -1;
        }
    }

    __syncthreads();
    unsigned long long vm = (unsigned long long)s_vm[0]
                          | ((unsigned long long)s_vm[1] << 32);
    const int nv = min((int)(__ffsll(~vm) - 1), MAXT);   // first invalid = count
    unsigned long long pm = (unsigned long long)s_pm[0]
                          | ((unsigned long long)s_pm[1] << 32);
    pm &= (nv >= 64) ? ~0ull : ((1ull << nv) - 1ull);    // only valid targets
    const int nvc = __popcll(pm);

    // ===== Compaction (order-preserving; writers use their own registers) ==
    if (tid < MAXT && ((pm >> tid) & 1ull)) {
        int rank = __popcll(pm & ((1ull << tid) - 1ull));
        s_cbox[rank] = my_box;
        s_ctk[rank]  = make_float2(my_thr, __int_as_float(my_key));
        s_cidx[rank] = tid;
    }
    if (tid < 4) {   // benign pads for unroll-4 overread
        s_cbox[nvc + tid] = make_float4(0.f, 0.f, 0.f, 0.f);
        s_ctk[nvc + tid]  = make_float2(1e30f, __int_as_float(-2));
        s_cidx[nvc + tid] = 0;
    }
    __syncthreads();

    // ---- Hot loop over pruned targets (avg ~3 instead of ~10.5) ----------
    #pragma unroll 4
    for (int t = 0; t < nvc; t++) {
        float4 b4 = s_cbox[t];
        float2 tk = s_ctk[t];
        int    tkey = __float_as_int(tk.y);
        int    tidx = s_cidx[t];
        #pragma unroll
        for (int k = 0; k < CPT; k++) {
            float cw  = fminf(px2[k], b4.z) - fmaxf(px1[k], b4.x);
            float chh = fminf(py2[k], b4.w) - fmaxf(py1[k], b4.y);
            float inter = fmaxf(cw, 0.0f) * fmaxf(chh, 0.0f);
            kill[k] = kill[k] | (inter > thrp[k] + tk.x);
            if (tkey == keyi[k]) owner[k] = tidx;   // last valid target wins
        }
    }

    // ---- Epilogue per cell ----
    float contrib = 0.0f, ce = 0.0f;
    int   nobj = 0;
    int   tcv[CPT];
    bool  isobj[CPT];

    #pragma unroll
    for (int k = 0; k < CPT; k++) {
        isobj[k] = false; tcv[k] = 0;
        if (owner[k] >= 0) {
            const int o = owner[k];
            // rare path: reload raw preds (L2-hot) and recompute exactly
            const float* bp = pred + off[k];
            float x  = bp[0];
            float yv = bp[SPATIAL];
            float w  = bp[2*SPATIAL];
            float h  = bp[3*SPATIAL];
            float sx = fsigmoid(x);
            float sy = fsigmoid(yv);
            const int a = keyi[k] / SPATIAL;
            float bw = __expf(w) * c_anch[2*a];
            float bh = __expf(h) * c_anch[2*a+1];
            float parea = bw * bh;
            float4 b4 = s_box[o];
            float cw  = fminf(px2[k], b4.z) - fmaxf(px1[k], b4.x);
            float chh = fminf(py2[k], b4.w) - fmaxf(py1[k], b4.y);
            float inter = (cw > 0.0f && chh > 0.0f) ? cw * chh : 0.0f;
            float uni   = parea + s_area[o] - inter;
            float tconf = (uni > 0.0f) ? __fdividef(inter, uni) : 0.0f;
            float dx = sx - s_tx[o];
            float dy = sy - s_ty[o];
            float dw = w  - s_tw[o];
            float dh = h  - s_th[o];
            contrib += dx*dx + dy*dy + dw*dw + dh*dh;     // COORD_SCALE = 1
            float dc = scv[k] - tconf;
            contrib += 5.0f * dc * dc;                     // OBJ_SCALE = 5
            tcv[k] = s_cls[o];
            isobj[k] = true;
            nobj++;
        } else if (!kill[k]) {
            contrib += scv[k] * scv[k];                    // NOOBJ, tconf = 0
        }
    }

    // ---- Warp-cooperative cross-entropy for obj cells (rare) ----
    const int lane = tid & 31;
    #pragma unroll
    for (int k = 0; k < CPT; k++) {
        unsigned int omask = __ballot_sync(FULLMASK, isobj[k]);
        while (omask) {
            int src = __ffs(omask) - 1;
            omask &= omask - 1;
            int offb = __shfl_sync(FULLMASK, off[k], src);
            int tcls = __shfl_sync(FULLMASK, tcv[k], src);
            const float* lg = pred + offb + 5*SPATIAL;

            float v0 = lg[(size_t)lane * SPATIAL];
            float v1 = lg[(size_t)(lane + 32) * SPATIAL];
            float v2 = (lane < NC - 64) ? lg[(size_t)(lane + 64) * SPATIAL] : -FLT_MAX;

            float m = fmaxf(fmaxf(v0, v1), v2);
            #pragma unroll
            for (int o = 16; o > 0; o >>= 1)
                m = fmaxf(m, __shfl_xor_sync(FULLMASK, m, o));

            float s = __expf(v0 - m) + __expf(v1 - m)
                    + ((lane < NC - 64) ? __expf(v2 - m) : 0.0f);
            #pragma unroll
            for (int o = 16; o > 0; o >>= 1)
                s += __shfl_xor_sync(FULLMASK, s, o);

            float tl_cand = (tcls < 32) ? v0 : ((tcls < 64) ? v1 : v2);
            float tl = __shfl_sync(FULLMASK, tl_cand, tcls & 31);

            float ce_val = (m + __logf(s)) - tl;
            if (lane == src) ce += ce_val;
        }
    }

    // ---- Block reduction -> global double atomics ----
    float r_main = contrib, r_ce = ce; int r_no = nobj;
    #pragma unroll
    for (int o = 16; o > 0; o >>= 1) {
        r_main += __shfl_down_sync(FULLMASK, r_main, o);
        r_ce   += __shfl_down_sync(FULLMASK, r_ce, o);
        r_no   += __shfl_down_sync(FULLMASK, r_no, o);
    }
    __shared__ float w0[BLOCK/32], w1[BLOCK/32];
    __shared__ int   w2[BLOCK/32];
    const int wid = tid >> 5;
    if (lane == 0) { w0[wid] = r_main; w1[wid] = r_ce; w2[wid] = r_no; }
    __syncthreads();
    if (tid == 0) {
        float a0 = 0.f, a1 = 0.f; int a2 = 0;
        #pragma unroll
        for (int k = 0; k < BLOCK/32; k++) { a0 += w0[k]; a1 += w1[k]; a2 += w2[k]; }
        atomicAdd(&g_main, (double)a0);
        if (a1 != 0.0f) atomicAdd(&g_ce, (double)a1);
        if (a2)         atomicAdd(&g_nobj, a2);
        __threadfence();
        unsigned int t = atomicAdd(&g_ticket, 1u);
        if (t == NBLK - 1) {
            __threadfence();
            double sm = g_main, scc = g_ce;
            double n = (double)g_nobj;
            if (n < 1.0) n = 1.0;
            out[0] = (float)(sm + scc / n);
            g_main = 0.0; g_ce = 0.0; g_nobj = 0;    // reset for next replay
            __threadfence();
            g_ticket = 0;
        }
    }
}

extern "C" void kernel_launch(void* const* d_in, const int* in_sizes, int n_in,
                              void* d_out, int out_size) {
    const float* pred = (const float*)d_in[0];
    const float* tgt  = (const float*)d_in[1];
    dim3 grid(BLOCKS_PER_B, BATCH);
    yolo_k<<<grid, BLOCK>>>(pred, tgt, (float*)d_out);
}